// round 1
// baseline (speedup 1.0000x reference)
#include <cuda_runtime.h>
#include <math.h>

#define BB   4
#define LQd  1024
#define CCd  256
#define HHd  8
#define DHd  32
#define LLd  4
#define PPd  4
#define DFFd 1024
#define LSRCd 21760
#define BQd  (BB*LQd)   // 4096

// ------------------------- scratch (device globals; no allocs) ---------------
__device__ float g_qk   [BQd*CCd];
__device__ float g_q    [BQd*CCd];
__device__ float g_k    [BQd*CCd];
__device__ float g_v    [BQd*CCd];
__device__ float g_S    [(size_t)BB*HHd*LQd*LQd];   // 128 MB attention scores
__device__ float g_o    [BQd*CCd];
__device__ float g_t2   [BQd*CCd];
__device__ float g_tgt1 [BQd*CCd];
__device__ float g_query[BQd*CCd];
__device__ float g_value[(size_t)BB*LSRCd*CCd];     // 89 MB
__device__ float g_off  [BQd*CCd];
__device__ float g_aw   [BQd*HHd*LLd*PPd];
__device__ float g_samp [BQd*CCd];
__device__ float g_tgt2 [BQd*CCd];
__device__ float g_ffn  [BQd*DFFd];

// ------------------------- elementwise add -----------------------------------
__global__ void vec_add(const float* __restrict__ a, const float* __restrict__ b,
                        float* __restrict__ c, int n) {
    int i = blockIdx.x * blockDim.x + threadIdx.x;
    if (i < n) c[i] = a[i] + b[i];
}

// ------------------------- SGEMM: C = A @ W^T + bias --------------------------
// A: (M,K) row-major, W: (N,K) row-major. BM=BN=128, BK=8, 256 thr, 8x8/thread.
// Requires: M%128==0, N%128==0, K%8==0, 16B-aligned pointers (all true here).
__global__ void gemm128(const float* __restrict__ A, const float* __restrict__ W,
                        const float* __restrict__ bias, float* __restrict__ C,
                        int M, int N, int K, int relu)
{
    __shared__ float As[8][132];
    __shared__ float Ws[8][132];
    const int tid = threadIdx.x;
    const int tx = tid & 15, ty = tid >> 4;
    const int m0 = blockIdx.y * 128, n0 = blockIdx.x * 128;
    const int r = tid >> 1, c = (tid & 1) * 4;
    float acc[8][8];
#pragma unroll
    for (int i = 0; i < 8; i++)
#pragma unroll
        for (int j = 0; j < 8; j++) acc[i][j] = 0.f;

    const float* Ap = A + (size_t)(m0 + r) * K + c;
    const float* Wp = W + (size_t)(n0 + r) * K + c;

    for (int k0 = 0; k0 < K; k0 += 8) {
        float4 av = *(const float4*)(Ap + k0);
        float4 wv = *(const float4*)(Wp + k0);
        As[c + 0][r] = av.x; As[c + 1][r] = av.y; As[c + 2][r] = av.z; As[c + 3][r] = av.w;
        Ws[c + 0][r] = wv.x; Ws[c + 1][r] = wv.y; Ws[c + 2][r] = wv.z; Ws[c + 3][r] = wv.w;
        __syncthreads();
#pragma unroll
        for (int kk = 0; kk < 8; kk++) {
            float a[8], w[8];
            *(float4*)(a)     = *(const float4*)&As[kk][ty * 4];
            *(float4*)(a + 4) = *(const float4*)&As[kk][64 + ty * 4];
            *(float4*)(w)     = *(const float4*)&Ws[kk][tx * 4];
            *(float4*)(w + 4) = *(const float4*)&Ws[kk][64 + tx * 4];
#pragma unroll
            for (int i = 0; i < 8; i++)
#pragma unroll
                for (int j = 0; j < 8; j++) acc[i][j] += a[i] * w[j];
        }
        __syncthreads();
    }

#pragma unroll
    for (int i = 0; i < 8; i++) {
        int m = m0 + ((i < 4) ? (ty * 4 + i) : (64 + ty * 4 + i - 4));
#pragma unroll
        for (int jj = 0; jj < 2; jj++) {
            int n = n0 + ((jj == 0) ? (tx * 4) : (64 + tx * 4));
            float4 o;
            o.x = acc[i][jj * 4 + 0] + bias[n + 0];
            o.y = acc[i][jj * 4 + 1] + bias[n + 1];
            o.z = acc[i][jj * 4 + 2] + bias[n + 2];
            o.w = acc[i][jj * 4 + 3] + bias[n + 3];
            if (relu) {
                o.x = fmaxf(o.x, 0.f); o.y = fmaxf(o.y, 0.f);
                o.z = fmaxf(o.z, 0.f); o.w = fmaxf(o.w, 0.f);
            }
            *(float4*)&C[(size_t)m * N + n] = o;
        }
    }
}

// ------------------------- attention: scores ---------------------------------
// grid (k-tiles=32, q-tiles=32, B*H=32), block (32,32)
__global__ void attn_scores(const float* __restrict__ q, const float* __restrict__ k,
                            float* __restrict__ S)
{
    __shared__ float qs[32][33], ks[32][33];
    int bh = blockIdx.z, b = bh >> 3, h = bh & 7;
    int q0 = blockIdx.y * 32, k0 = blockIdx.x * 32;
    int tx = threadIdx.x, ty = threadIdx.y;
    qs[ty][tx] = q[(size_t)(b * LQd + q0 + ty) * CCd + h * DHd + tx];
    ks[ty][tx] = k[(size_t)(b * LQd + k0 + ty) * CCd + h * DHd + tx];
    __syncthreads();
    float s = 0.f;
#pragma unroll
    for (int d = 0; d < 32; d++) s += qs[ty][d] * ks[tx][d];
    S[((size_t)bh * LQd + q0 + ty) * LQd + k0 + tx] = s * 0.1767766952966368932f;
}

// ------------------------- softmax over rows of 1024 -------------------------
__global__ void softmax_rows(float* __restrict__ S)
{
    __shared__ float sh[256];
    size_t row = blockIdx.x;
    float* p = S + row * LQd;
    int t = threadIdx.x;
    float x[4];
    float m = -1e30f;
#pragma unroll
    for (int i = 0; i < 4; i++) { x[i] = p[t + i * 256]; m = fmaxf(m, x[i]); }
    sh[t] = m; __syncthreads();
    for (int s = 128; s > 0; s >>= 1) { if (t < s) sh[t] = fmaxf(sh[t], sh[t + s]); __syncthreads(); }
    m = sh[0]; __syncthreads();
    float sum = 0.f;
#pragma unroll
    for (int i = 0; i < 4; i++) { x[i] = __expf(x[i] - m); sum += x[i]; }
    sh[t] = sum; __syncthreads();
    for (int s = 128; s > 0; s >>= 1) { if (t < s) sh[t] += sh[t + s]; __syncthreads(); }
    float inv = 1.f / sh[0];
#pragma unroll
    for (int i = 0; i < 4; i++) p[t + i * 256] = x[i] * inv;
}

// ------------------------- attention: O = S @ V ------------------------------
// grid (q-tiles=32, B*H=32), block (32,32): tx = channel d, ty = local query
__global__ void attn_av(const float* __restrict__ S, const float* __restrict__ v,
                        float* __restrict__ O)
{
    __shared__ float Ss[32][33], Vs[32][33];
    int bh = blockIdx.y, b = bh >> 3, h = bh & 7;
    int q0 = blockIdx.x * 32;
    int tx = threadIdx.x, ty = threadIdx.y;
    float acc = 0.f;
    for (int k0 = 0; k0 < LQd; k0 += 32) {
        Ss[ty][tx] = S[((size_t)bh * LQd + q0 + ty) * LQd + k0 + tx];
        Vs[ty][tx] = v[(size_t)(b * LQd + k0 + ty) * CCd + h * DHd + tx];
        __syncthreads();
#pragma unroll
        for (int kk = 0; kk < 32; kk++) acc += Ss[ty][kk] * Vs[kk][tx];
        __syncthreads();
    }
    O[(size_t)(b * LQd + q0 + ty) * CCd + h * DHd + tx] = acc;
}

// ------------------------- fused residual + LayerNorm ------------------------
// one block per row of C=256, 256 threads
__global__ void add_ln(const float* __restrict__ a, const float* __restrict__ b,
                       const float* __restrict__ g, const float* __restrict__ bet,
                       float* __restrict__ out)
{
    __shared__ float sh[256];
    int row = blockIdx.x, t = threadIdx.x;
    size_t idx = (size_t)row * CCd + t;
    float v = a[idx] + b[idx];
    sh[t] = v; __syncthreads();
    for (int s = 128; s > 0; s >>= 1) { if (t < s) sh[t] += sh[t + s]; __syncthreads(); }
    float mean = sh[0] * (1.f / 256.f);
    __syncthreads();
    float d = v - mean;
    sh[t] = d * d; __syncthreads();
    for (int s = 128; s > 0; s >>= 1) { if (t < s) sh[t] += sh[t + s]; __syncthreads(); }
    float var = sh[0] * (1.f / 256.f);
    out[idx] = d * rsqrtf(var + 1e-5f) * g[t] + bet[t];
}

// ------------------------- attention-weight softmax over L*P=16 --------------
__global__ void aw_softmax(float* __restrict__ a)
{
    int gi = blockIdx.x * blockDim.x + threadIdx.x;
    if (gi >= BQd * HHd) return;
    float* p = a + (size_t)gi * 16;
    float x[16];
    float m = -1e30f;
#pragma unroll
    for (int i = 0; i < 16; i++) { x[i] = p[i]; m = fmaxf(m, x[i]); }
    float s = 0.f;
#pragma unroll
    for (int i = 0; i < 16; i++) { x[i] = __expf(x[i] - m); s += x[i]; }
    float inv = 1.f / s;
#pragma unroll
    for (int i = 0; i < 16; i++) p[i] = x[i] * inv;
}

// ------------------------- multi-scale deformable sampling -------------------
// one warp per (b,q,h): lane = channel d. block = 256 thr = 8 warps = all heads
__global__ void deform_sample(const float* __restrict__ value, const float* __restrict__ ref,
                              const float* __restrict__ off, const float* __restrict__ aw,
                              float* __restrict__ out)
{
    const int levH[4] = {128, 64, 32, 16};
    const int levW[4] = {128, 64, 32, 16};
    const int levS[4] = {0, 16384, 20480, 21504};
    int bq = blockIdx.x;              // b*LQ + q
    int b  = bq >> 10;
    int h  = threadIdx.x >> 5;
    int d  = threadIdx.x & 31;
    float acc = 0.f;
#pragma unroll
    for (int l = 0; l < 4; l++) {
        float rx = ref[((size_t)bq * LLd + l) * 2 + 0];
        float ry = ref[((size_t)bq * LLd + l) * 2 + 1];
        int w = levW[l], hh = levH[l], st = levS[l];
        float fw = (float)w, fh = (float)hh;
#pragma unroll
        for (int p = 0; p < 4; p++) {
            size_t oidx = ((((size_t)bq * HHd + h) * LLd + l) * PPd + p) * 2;
            float lx = rx + off[oidx]     / fw;
            float ly = ry + off[oidx + 1] / fh;
            float x = lx * fw - 0.5f;
            float y = ly * fh - 0.5f;
            float x0f = floorf(x), y0f = floorf(y);
            int x0 = (int)x0f, y0 = (int)y0f;
            float wx1 = x - x0f, wx0 = 1.f - wx1;
            float wy1 = y - y0f, wy0 = 1.f - wy1;
            float a = aw[((size_t)bq * HHd + h) * 16 + l * 4 + p];
            float s = 0.f;
#pragma unroll
            for (int cy = 0; cy < 2; cy++) {
#pragma unroll
                for (int cx = 0; cx < 2; cx++) {
                    int ix = x0 + cx, iy = y0 + cy;
                    if (ix >= 0 && ix < w && iy >= 0 && iy < hh) {
                        float wgt = (cx ? wx1 : wx0) * (cy ? wy1 : wy0);
                        size_t vidx = (((size_t)(b * LSRCd + st + iy * w + ix)) * HHd + h) * DHd + d;
                        s += wgt * value[vidx];
                    }
                }
            }
            acc += a * s;
        }
    }
    out[(size_t)bq * CCd + h * DHd + d] = acc;
}

// ------------------------- launch --------------------------------------------
extern "C" void kernel_launch(void* const* d_in, const int* in_sizes, int n_in,
                              void* d_out, int out_size)
{
    (void)in_sizes; (void)n_in; (void)out_size;
    const float* tgt   = (const float*)d_in[0];
    const float* qpos  = (const float*)d_in[1];
    const float* ref   = (const float*)d_in[2];
    const float* src   = (const float*)d_in[3];
    const float* in_w  = (const float*)d_in[4];
    const float* in_b  = (const float*)d_in[5];
    const float* sa_w  = (const float*)d_in[6];
    const float* sa_b  = (const float*)d_in[7];
    const float* off_w = (const float*)d_in[8];
    const float* off_b = (const float*)d_in[9];
    const float* aw_w  = (const float*)d_in[10];
    const float* aw_b  = (const float*)d_in[11];
    const float* val_w = (const float*)d_in[12];
    const float* val_b = (const float*)d_in[13];
    const float* co_w  = (const float*)d_in[14];
    const float* co_b  = (const float*)d_in[15];
    const float* ln1_g = (const float*)d_in[16];
    const float* ln1_b = (const float*)d_in[17];
    const float* ln2_g = (const float*)d_in[18];
    const float* ln2_b = (const float*)d_in[19];
    const float* ln3_g = (const float*)d_in[20];
    const float* ln3_b = (const float*)d_in[21];
    const float* f1_w  = (const float*)d_in[22];
    const float* f1_b  = (const float*)d_in[23];
    const float* f2_w  = (const float*)d_in[24];
    const float* f2_b  = (const float*)d_in[25];
    float* out = (float*)d_out;

    float *qk, *q, *k, *v, *S, *o, *t2, *tgt1, *query, *value, *off, *aw, *samp, *tgt2, *ffn;
    cudaGetSymbolAddress((void**)&qk,    g_qk);
    cudaGetSymbolAddress((void**)&q,     g_q);
    cudaGetSymbolAddress((void**)&k,     g_k);
    cudaGetSymbolAddress((void**)&v,     g_v);
    cudaGetSymbolAddress((void**)&S,     g_S);
    cudaGetSymbolAddress((void**)&o,     g_o);
    cudaGetSymbolAddress((void**)&t2,    g_t2);
    cudaGetSymbolAddress((void**)&tgt1,  g_tgt1);
    cudaGetSymbolAddress((void**)&query, g_query);
    cudaGetSymbolAddress((void**)&value, g_value);
    cudaGetSymbolAddress((void**)&off,   g_off);
    cudaGetSymbolAddress((void**)&aw,    g_aw);
    cudaGetSymbolAddress((void**)&samp,  g_samp);
    cudaGetSymbolAddress((void**)&tgt2,  g_tgt2);
    cudaGetSymbolAddress((void**)&ffn,   g_ffn);

    const int NTOT = BQd * CCd;

    // ---- self-attention ----
    vec_add<<<NTOT / 256, 256>>>(tgt, qpos, qk, NTOT);
    gemm128<<<dim3(2, 32), 256>>>(qk,  in_w,                 in_b,           q, BQd, CCd, CCd, 0);
    gemm128<<<dim3(2, 32), 256>>>(qk,  in_w + CCd * CCd,     in_b + CCd,     k, BQd, CCd, CCd, 0);
    gemm128<<<dim3(2, 32), 256>>>(tgt, in_w + 2 * CCd * CCd, in_b + 2 * CCd, v, BQd, CCd, CCd, 0);
    attn_scores<<<dim3(32, 32, 32), dim3(32, 32)>>>(q, k, S);
    softmax_rows<<<BB * HHd * LQd, 256>>>(S);
    attn_av<<<dim3(32, 32), dim3(32, 32)>>>(S, v, o);
    gemm128<<<dim3(2, 32), 256>>>(o, sa_w, sa_b, t2, BQd, CCd, CCd, 0);
    add_ln<<<BQd, 256>>>(tgt, t2, ln2_g, ln2_b, tgt1);

    // ---- deformable cross-attention ----
    vec_add<<<NTOT / 256, 256>>>(tgt1, qpos, query, NTOT);
    gemm128<<<dim3(2, 680), 256>>>(src, val_w, val_b, value, BB * LSRCd, CCd, CCd, 0);
    gemm128<<<dim3(2, 32), 256>>>(query, off_w, off_b, off, BQd, CCd, CCd, 0);
    gemm128<<<dim3(1, 32), 256>>>(query, aw_w, aw_b, aw, BQd, HHd * LLd * PPd, CCd, 0);
    aw_softmax<<<(BQd * HHd + 255) / 256, 256>>>(aw);
    deform_sample<<<BQd, 256>>>(value, ref, off, aw, samp);
    gemm128<<<dim3(2, 32), 256>>>(samp, co_w, co_b, t2, BQd, CCd, CCd, 0);
    add_ln<<<BQd, 256>>>(tgt1, t2, ln1_g, ln1_b, tgt2);

    // ---- FFN ----
    gemm128<<<dim3(8, 32), 256>>>(tgt2, f1_w, f1_b, ffn, BQd, DFFd, CCd, 1);
    gemm128<<<dim3(2, 32), 256>>>(ffn, f2_w, f2_b, t2, BQd, CCd, DFFd, 0);
    add_ln<<<BQd, 256>>>(tgt2, t2, ln3_g, ln3_b, out);
}

// round 4
// speedup vs baseline: 2.0896x; 2.0896x over previous
#include <cuda_runtime.h>
#include <math.h>

#define BB   4
#define LQd  1024
#define CCd  256
#define HHd  8
#define DHd  32
#define LLd  4
#define PPd  4
#define DFFd 1024
#define LSRCd 21760
#define BQd  (BB*LQd)   // 4096

// ------------------------- scratch (device globals; no allocs) ---------------
__device__ float g_qk    [BQd*CCd];
__device__ float g_qkproj[BQd*512];          // fused Q|K projection
__device__ float g_v     [BQd*CCd];
__device__ float g_o     [BQd*CCd];
__device__ float g_t2    [BQd*CCd];
__device__ float g_tgt1  [BQd*CCd];
__device__ float g_query [BQd*CCd];
__device__ float g_value [(size_t)BB*LSRCd*CCd];   // 89 MB
__device__ float g_offaw [BQd*384];          // fused offsets|attn-weights
__device__ float g_woffaw[384*CCd];
__device__ float g_boffaw[384];
__device__ float g_samp  [BQd*CCd];
__device__ float g_tgt2  [BQd*CCd];
__device__ float g_ffn   [BQd*DFFd];

// ------------------------- elementwise add -----------------------------------
__global__ void vec_add(const float* __restrict__ a, const float* __restrict__ b,
                        float* __restrict__ c, int n) {
    int i = blockIdx.x * blockDim.x + threadIdx.x;
    if (i < n) c[i] = a[i] + b[i];
}

// ------------------------- SGEMM 128x128, BK=8, double-buffered --------------
// C = A @ W^T + bias.  A:(M,K) row-major, W:(N,K) row-major. 256 thr, 8x8/thr.
__global__ void gemm128(const float* __restrict__ A, const float* __restrict__ W,
                        const float* __restrict__ bias, float* __restrict__ C,
                        int M, int N, int K, int relu)
{
    __shared__ __align__(16) float As[2][8][132];
    __shared__ __align__(16) float Ws[2][8][132];
    const int tid = threadIdx.x;
    const int tx = tid & 15, ty = tid >> 4;
    const int m0 = blockIdx.y * 128, n0 = blockIdx.x * 128;
    const int r = tid >> 1, c = (tid & 1) * 4;
    float acc[8][8];
#pragma unroll
    for (int i = 0; i < 8; i++)
#pragma unroll
        for (int j = 0; j < 8; j++) acc[i][j] = 0.f;

    const float* Ap = A + (size_t)(m0 + r) * K + c;
    const float* Wp = W + (size_t)(n0 + r) * K + c;

    float4 av = *(const float4*)(Ap);
    float4 wv = *(const float4*)(Wp);
    As[0][c + 0][r] = av.x; As[0][c + 1][r] = av.y; As[0][c + 2][r] = av.z; As[0][c + 3][r] = av.w;
    Ws[0][c + 0][r] = wv.x; Ws[0][c + 1][r] = wv.y; Ws[0][c + 2][r] = wv.z; Ws[0][c + 3][r] = wv.w;
    __syncthreads();

    int buf = 0;
    for (int k0 = 8; k0 < K; k0 += 8) {
        float4 av2 = *(const float4*)(Ap + k0);
        float4 wv2 = *(const float4*)(Wp + k0);
#pragma unroll
        for (int kk = 0; kk < 8; kk++) {
            float a[8], w[8];
            *(float4*)(a)     = *(const float4*)&As[buf][kk][ty * 4];
            *(float4*)(a + 4) = *(const float4*)&As[buf][kk][64 + ty * 4];
            *(float4*)(w)     = *(const float4*)&Ws[buf][kk][tx * 4];
            *(float4*)(w + 4) = *(const float4*)&Ws[buf][kk][64 + tx * 4];
#pragma unroll
            for (int i = 0; i < 8; i++)
#pragma unroll
                for (int j = 0; j < 8; j++) acc[i][j] += a[i] * w[j];
        }
        buf ^= 1;
        As[buf][c + 0][r] = av2.x; As[buf][c + 1][r] = av2.y; As[buf][c + 2][r] = av2.z; As[buf][c + 3][r] = av2.w;
        Ws[buf][c + 0][r] = wv2.x; Ws[buf][c + 1][r] = wv2.y; Ws[buf][c + 2][r] = wv2.z; Ws[buf][c + 3][r] = wv2.w;
        __syncthreads();
    }
#pragma unroll
    for (int kk = 0; kk < 8; kk++) {
        float a[8], w[8];
        *(float4*)(a)     = *(const float4*)&As[buf][kk][ty * 4];
        *(float4*)(a + 4) = *(const float4*)&As[buf][kk][64 + ty * 4];
        *(float4*)(w)     = *(const float4*)&Ws[buf][kk][tx * 4];
        *(float4*)(w + 4) = *(const float4*)&Ws[buf][kk][64 + tx * 4];
#pragma unroll
        for (int i = 0; i < 8; i++)
#pragma unroll
            for (int j = 0; j < 8; j++) acc[i][j] += a[i] * w[j];
    }

#pragma unroll
    for (int i = 0; i < 8; i++) {
        int m = m0 + ((i < 4) ? (ty * 4 + i) : (64 + ty * 4 + i - 4));
#pragma unroll
        for (int jj = 0; jj < 2; jj++) {
            int n = n0 + ((jj == 0) ? (tx * 4) : (64 + tx * 4));
            float4 o;
            o.x = acc[i][jj * 4 + 0] + bias[n + 0];
            o.y = acc[i][jj * 4 + 1] + bias[n + 1];
            o.z = acc[i][jj * 4 + 2] + bias[n + 2];
            o.w = acc[i][jj * 4 + 3] + bias[n + 3];
            if (relu) {
                o.x = fmaxf(o.x, 0.f); o.y = fmaxf(o.y, 0.f);
                o.z = fmaxf(o.z, 0.f); o.w = fmaxf(o.w, 0.f);
            }
            *(float4*)&C[(size_t)m * N + n] = o;
        }
    }
}

// ------------------------- SGEMM 64x64, BK=16, double-buffered ---------------
// For small-N projections: high CTA count, low registers.
__global__ void gemm64(const float* __restrict__ A, const float* __restrict__ W,
                       const float* __restrict__ bias, float* __restrict__ C,
                       int M, int N, int K, int relu)
{
    __shared__ __align__(16) float As[2][16][68];
    __shared__ __align__(16) float Ws[2][16][68];
    const int tid = threadIdx.x;           // 256
    const int tx = tid & 15, ty = tid >> 4;
    const int m0 = blockIdx.y * 64, n0 = blockIdx.x * 64;
    const int r = tid >> 2, c = (tid & 3) * 4;   // 64 rows x 16 cols
    float acc[4][4];
#pragma unroll
    for (int i = 0; i < 4; i++)
#pragma unroll
        for (int j = 0; j < 4; j++) acc[i][j] = 0.f;

    const float* Ap = A + (size_t)(m0 + r) * K + c;
    const float* Wp = W + (size_t)(n0 + r) * K + c;

    float4 av = *(const float4*)(Ap);
    float4 wv = *(const float4*)(Wp);
    As[0][c + 0][r] = av.x; As[0][c + 1][r] = av.y; As[0][c + 2][r] = av.z; As[0][c + 3][r] = av.w;
    Ws[0][c + 0][r] = wv.x; Ws[0][c + 1][r] = wv.y; Ws[0][c + 2][r] = wv.z; Ws[0][c + 3][r] = wv.w;
    __syncthreads();

    int buf = 0;
    for (int k0 = 16; k0 < K; k0 += 16) {
        float4 av2 = *(const float4*)(Ap + k0);
        float4 wv2 = *(const float4*)(Wp + k0);
#pragma unroll
        for (int kk = 0; kk < 16; kk++) {
            float a[4], w[4];
            *(float4*)(a) = *(const float4*)&As[buf][kk][ty * 4];
            *(float4*)(w) = *(const float4*)&Ws[buf][kk][tx * 4];
#pragma unroll
            for (int i = 0; i < 4; i++)
#pragma unroll
                for (int j = 0; j < 4; j++) acc[i][j] += a[i] * w[j];
        }
        buf ^= 1;
        As[buf][c + 0][r] = av2.x; As[buf][c + 1][r] = av2.y; As[buf][c + 2][r] = av2.z; As[buf][c + 3][r] = av2.w;
        Ws[buf][c + 0][r] = wv2.x; Ws[buf][c + 1][r] = wv2.y; Ws[buf][c + 2][r] = wv2.z; Ws[buf][c + 3][r] = wv2.w;
        __syncthreads();
    }
#pragma unroll
    for (int kk = 0; kk < 16; kk++) {
        float a[4], w[4];
        *(float4*)(a) = *(const float4*)&As[buf][kk][ty * 4];
        *(float4*)(w) = *(const float4*)&Ws[buf][kk][tx * 4];
#pragma unroll
        for (int i = 0; i < 4; i++)
#pragma unroll
            for (int j = 0; j < 4; j++) acc[i][j] += a[i] * w[j];
    }

#pragma unroll
    for (int i = 0; i < 4; i++) {
        int m = m0 + ty * 4 + i;
        int n = n0 + tx * 4;
        float4 o;
        o.x = acc[i][0] + bias[n + 0];
        o.y = acc[i][1] + bias[n + 1];
        o.z = acc[i][2] + bias[n + 2];
        o.w = acc[i][3] + bias[n + 3];
        if (relu) {
            o.x = fmaxf(o.x, 0.f); o.y = fmaxf(o.y, 0.f);
            o.z = fmaxf(o.z, 0.f); o.w = fmaxf(o.w, 0.f);
        }
        *(float4*)&C[(size_t)m * N + n] = o;
    }
}

// ------------------------- flash attention -----------------------------------
// grid (LQ/64=16, B*H=32), block 256. Q,K from fused proj (stride 512), V stride 256.
// NOTE all smem row strides are multiples of 4 floats so float4 reads are 16B-aligned.
__global__ void flash_attn(const float* __restrict__ qkproj, const float* __restrict__ vsrc,
                           float* __restrict__ O)
{
    __shared__ __align__(16) float Qs[32][68];
    __shared__ __align__(16) float Ks[32][68];
    __shared__ __align__(16) float Vs[64][36];
    __shared__ __align__(16) float Ps[64][68];
    const int bh = blockIdx.y, b = bh >> 3, h = bh & 7;
    const int q0 = blockIdx.x * 64;
    const int tid = threadIdx.x;
    const int tx = tid & 15, ty = tid >> 4;
    const float SC = 0.1767766952966368932f;

    const float* qp = qkproj + (size_t)b * LQd * 512 + h * DHd;
    const float* kp = qkproj + (size_t)b * LQd * 512 + 256 + h * DHd;
    const float* vp = vsrc + (size_t)b * LQd * CCd + h * DHd;

#pragma unroll
    for (int i = 0; i < 8; i++) {
        int idx = tid + i * 256;
        int row = idx >> 5, d = idx & 31;
        Qs[d][row] = qp[(size_t)(q0 + row) * 512 + d];
    }
    float m_r[4], l_r[4], o_acc[4][2];
#pragma unroll
    for (int i = 0; i < 4; i++) { m_r[i] = -1e30f; l_r[i] = 0.f; o_acc[i][0] = 0.f; o_acc[i][1] = 0.f; }
    __syncthreads();

    for (int k0 = 0; k0 < LQd; k0 += 64) {
#pragma unroll
        for (int i = 0; i < 8; i++) {
            int idx = tid + i * 256;
            int row = idx >> 5, d = idx & 31;
            Ks[d][row] = kp[(size_t)(k0 + row) * 512 + d];
            Vs[row][d] = vp[(size_t)(k0 + row) * CCd + d];
        }
        __syncthreads();

        float s[4][4];
#pragma unroll
        for (int i = 0; i < 4; i++)
#pragma unroll
            for (int j = 0; j < 4; j++) s[i][j] = 0.f;
#pragma unroll
        for (int d = 0; d < 32; d++) {
            float a[4], w[4];
            *(float4*)(a) = *(const float4*)&Qs[d][ty * 4];
            *(float4*)(w) = *(const float4*)&Ks[d][tx * 4];
#pragma unroll
            for (int i = 0; i < 4; i++)
#pragma unroll
                for (int j = 0; j < 4; j++) s[i][j] += a[i] * w[j];
        }

#pragma unroll
        for (int i = 0; i < 4; i++) {
#pragma unroll
            for (int j = 0; j < 4; j++) s[i][j] *= SC;
            float mx = fmaxf(fmaxf(s[i][0], s[i][1]), fmaxf(s[i][2], s[i][3]));
            mx = fmaxf(mx, __shfl_xor_sync(0xffffffffu, mx, 1));
            mx = fmaxf(mx, __shfl_xor_sync(0xffffffffu, mx, 2));
            mx = fmaxf(mx, __shfl_xor_sync(0xffffffffu, mx, 4));
            mx = fmaxf(mx, __shfl_xor_sync(0xffffffffu, mx, 8));
            float mnew = fmaxf(m_r[i], mx);
            float cf = __expf(m_r[i] - mnew);
            float p0 = __expf(s[i][0] - mnew);
            float p1 = __expf(s[i][1] - mnew);
            float p2 = __expf(s[i][2] - mnew);
            float p3 = __expf(s[i][3] - mnew);
            float4 pv4 = make_float4(p0, p1, p2, p3);
            *(float4*)&Ps[ty * 4 + i][tx * 4] = pv4;
            float rs = p0 + p1 + p2 + p3;
            rs += __shfl_xor_sync(0xffffffffu, rs, 1);
            rs += __shfl_xor_sync(0xffffffffu, rs, 2);
            rs += __shfl_xor_sync(0xffffffffu, rs, 4);
            rs += __shfl_xor_sync(0xffffffffu, rs, 8);
            l_r[i] = l_r[i] * cf + rs;
            o_acc[i][0] *= cf; o_acc[i][1] *= cf;
            m_r[i] = mnew;
        }
        __syncthreads();

#pragma unroll
        for (int kk4 = 0; kk4 < 16; kk4++) {
            float p[4][4];
#pragma unroll
            for (int i = 0; i < 4; i++)
                *(float4*)(p[i]) = *(const float4*)&Ps[ty * 4 + i][kk4 * 4];
#pragma unroll
            for (int j = 0; j < 4; j++) {
                float2 vv = *(const float2*)&Vs[kk4 * 4 + j][tx * 2];
#pragma unroll
                for (int i = 0; i < 4; i++) {
                    o_acc[i][0] += p[i][j] * vv.x;
                    o_acc[i][1] += p[i][j] * vv.y;
                }
            }
        }
        __syncthreads();
    }

#pragma unroll
    for (int i = 0; i < 4; i++) {
        float inv = 1.f / l_r[i];
        float2 ov = make_float2(o_acc[i][0] * inv, o_acc[i][1] * inv);
        *(float2*)&O[(size_t)(b * LQd + q0 + ty * 4 + i) * CCd + h * DHd + tx * 2] = ov;
    }
}

// ------------------------- fused residual + LayerNorm ------------------------
__global__ void add_ln(const float* __restrict__ a, const float* __restrict__ b,
                       const float* __restrict__ g, const float* __restrict__ bet,
                       float* __restrict__ out)
{
    __shared__ float sh[256];
    int row = blockIdx.x, t = threadIdx.x;
    size_t idx = (size_t)row * CCd + t;
    float v = a[idx] + b[idx];
    sh[t] = v; __syncthreads();
    for (int s = 128; s > 0; s >>= 1) { if (t < s) sh[t] += sh[t + s]; __syncthreads(); }
    float mean = sh[0] * (1.f / 256.f);
    __syncthreads();
    float d = v - mean;
    sh[t] = d * d; __syncthreads();
    for (int s = 128; s > 0; s >>= 1) { if (t < s) sh[t] += sh[t + s]; __syncthreads(); }
    float var = sh[0] * (1.f / 256.f);
    out[idx] = d * rsqrtf(var + 1e-5f) * g[t] + bet[t];
}

// ------------------------- attention-weight softmax over L*P=16 --------------
// reads/writes the aw section of the fused offaw buffer (row stride 384, +256)
__global__ void aw_softmax(float* __restrict__ a)
{
    int gi = blockIdx.x * blockDim.x + threadIdx.x;
    if (gi >= BQd * HHd) return;
    int bq = gi >> 3, h = gi & 7;
    float* p = a + (size_t)bq * 384 + 256 + h * 16;
    float x[16];
    float m = -1e30f;
#pragma unroll
    for (int i = 0; i < 16; i++) { x[i] = p[i]; m = fmaxf(m, x[i]); }
    float s = 0.f;
#pragma unroll
    for (int i = 0; i < 16; i++) { x[i] = __expf(x[i] - m); s += x[i]; }
    float inv = 1.f / s;
#pragma unroll
    for (int i = 0; i < 16; i++) p[i] = x[i] * inv;
}

// ------------------------- multi-scale deformable sampling -------------------
// one warp per (b,q,h): lane = channel d. off/aw in fused buffer (stride 384)
__global__ void deform_sample(const float* __restrict__ value, const float* __restrict__ ref,
                              const float* __restrict__ offaw, float* __restrict__ out)
{
    const int levH[4] = {128, 64, 32, 16};
    const int levW[4] = {128, 64, 32, 16};
    const int levS[4] = {0, 16384, 20480, 21504};
    int bq = blockIdx.x;
    int b  = bq >> 10;
    int h  = threadIdx.x >> 5;
    int d  = threadIdx.x & 31;
    float acc = 0.f;
#pragma unroll
    for (int l = 0; l < 4; l++) {
        float rx = ref[((size_t)bq * LLd + l) * 2 + 0];
        float ry = ref[((size_t)bq * LLd + l) * 2 + 1];
        int w = levW[l], hh = levH[l], st = levS[l];
        float fw = (float)w, fh = (float)hh;
#pragma unroll
        for (int p = 0; p < 4; p++) {
            size_t oidx = (size_t)bq * 384 + h * 32 + (l * 4 + p) * 2;
            float lx = rx + offaw[oidx]     / fw;
            float ly = ry + offaw[oidx + 1] / fh;
            float x = lx * fw - 0.5f;
            float y = ly * fh - 0.5f;
            float x0f = floorf(x), y0f = floorf(y);
            int x0 = (int)x0f, y0 = (int)y0f;
            float wx1 = x - x0f, wx0 = 1.f - wx1;
            float wy1 = y - y0f, wy0 = 1.f - wy1;
            float a = offaw[(size_t)bq * 384 + 256 + h * 16 + l * 4 + p];
            float s = 0.f;
#pragma unroll
            for (int cy = 0; cy < 2; cy++) {
#pragma unroll
                for (int cx = 0; cx < 2; cx++) {
                    int ix = x0 + cx, iy = y0 + cy;
                    if (ix >= 0 && ix < w && iy >= 0 && iy < hh) {
                        float wgt = (cx ? wx1 : wx0) * (cy ? wy1 : wy0);
                        size_t vidx = (((size_t)(b * LSRCd + st + iy * w + ix)) * HHd + h) * DHd + d;
                        s += wgt * value[vidx];
                    }
                }
            }
            acc += a * s;
        }
    }
    out[(size_t)bq * CCd + h * DHd + d] = acc;
}

// ------------------------- launch --------------------------------------------
extern "C" void kernel_launch(void* const* d_in, const int* in_sizes, int n_in,
                              void* d_out, int out_size)
{
    (void)in_sizes; (void)n_in; (void)out_size;
    const float* tgt   = (const float*)d_in[0];
    const float* qpos  = (const float*)d_in[1];
    const float* ref   = (const float*)d_in[2];
    const float* src   = (const float*)d_in[3];
    const float* in_w  = (const float*)d_in[4];
    const float* in_b  = (const float*)d_in[5];
    const float* sa_w  = (const float*)d_in[6];
    const float* sa_b  = (const float*)d_in[7];
    const float* off_w = (const float*)d_in[8];
    const float* off_b = (const float*)d_in[9];
    const float* aw_w  = (const float*)d_in[10];
    const float* aw_b  = (const float*)d_in[11];
    const float* val_w = (const float*)d_in[12];
    const float* val_b = (const float*)d_in[13];
    const float* co_w  = (const float*)d_in[14];
    const float* co_b  = (const float*)d_in[15];
    const float* ln1_g = (const float*)d_in[16];
    const float* ln1_b = (const float*)d_in[17];
    const float* ln2_g = (const float*)d_in[18];
    const float* ln2_b = (const float*)d_in[19];
    const float* ln3_g = (const float*)d_in[20];
    const float* ln3_b = (const float*)d_in[21];
    const float* f1_w  = (const float*)d_in[22];
    const float* f1_b  = (const float*)d_in[23];
    const float* f2_w  = (const float*)d_in[24];
    const float* f2_b  = (const float*)d_in[25];
    float* out = (float*)d_out;

    float *qk, *qkproj, *v, *o, *t2, *tgt1, *query, *value, *offaw, *woffaw, *boffaw, *samp, *tgt2, *ffn;
    cudaGetSymbolAddress((void**)&qk,     g_qk);
    cudaGetSymbolAddress((void**)&qkproj, g_qkproj);
    cudaGetSymbolAddress((void**)&v,      g_v);
    cudaGetSymbolAddress((void**)&o,      g_o);
    cudaGetSymbolAddress((void**)&t2,     g_t2);
    cudaGetSymbolAddress((void**)&tgt1,   g_tgt1);
    cudaGetSymbolAddress((void**)&query,  g_query);
    cudaGetSymbolAddress((void**)&value,  g_value);
    cudaGetSymbolAddress((void**)&offaw,  g_offaw);
    cudaGetSymbolAddress((void**)&woffaw, g_woffaw);
    cudaGetSymbolAddress((void**)&boffaw, g_boffaw);
    cudaGetSymbolAddress((void**)&samp,   g_samp);
    cudaGetSymbolAddress((void**)&tgt2,   g_tgt2);
    cudaGetSymbolAddress((void**)&ffn,    g_ffn);

    const int NTOT = BQd * CCd;

    // fuse off/aw weights into one (384,256) matrix + (384,) bias
    cudaMemcpyAsync(woffaw,             off_w, 256 * 256 * sizeof(float), cudaMemcpyDeviceToDevice);
    cudaMemcpyAsync(woffaw + 256 * 256, aw_w,  128 * 256 * sizeof(float), cudaMemcpyDeviceToDevice);
    cudaMemcpyAsync(boffaw,             off_b, 256 * sizeof(float),       cudaMemcpyDeviceToDevice);
    cudaMemcpyAsync(boffaw + 256,       aw_b,  128 * sizeof(float),       cudaMemcpyDeviceToDevice);

    // ---- self-attention ----
    vec_add<<<NTOT / 256, 256>>>(tgt, qpos, qk, NTOT);
    gemm128<<<dim3(4, 32), 256>>>(qk, in_w, in_b, qkproj, BQd, 512, CCd, 0);      // fused Q|K
    gemm64 <<<dim3(4, 64), 256>>>(tgt, in_w + 2 * CCd * CCd, in_b + 2 * CCd, v, BQd, CCd, CCd, 0);
    flash_attn<<<dim3(16, 32), 256>>>(qkproj, v, o);
    gemm64 <<<dim3(4, 64), 256>>>(o, sa_w, sa_b, t2, BQd, CCd, CCd, 0);
    add_ln<<<BQd, 256>>>(tgt, t2, ln2_g, ln2_b, tgt1);

    // ---- deformable cross-attention ----
    vec_add<<<NTOT / 256, 256>>>(tgt1, qpos, query, NTOT);
    gemm128<<<dim3(2, 680), 256>>>(src, val_w, val_b, value, BB * LSRCd, CCd, CCd, 0);
    gemm64 <<<dim3(6, 64), 256>>>(query, woffaw, boffaw, offaw, BQd, 384, CCd, 0); // fused off|aw
    aw_softmax<<<(BQd * HHd + 255) / 256, 256>>>(offaw);
    deform_sample<<<BQd, 256>>>(value, ref, offaw, samp);
    gemm64 <<<dim3(4, 64), 256>>>(samp, co_w, co_b, t2, BQd, CCd, CCd, 0);
    add_ln<<<BQd, 256>>>(tgt1, t2, ln1_g, ln1_b, tgt2);

    // ---- FFN ----
    gemm128<<<dim3(8, 32), 256>>>(tgt2, f1_w, f1_b, ffn, BQd, DFFd, CCd, 1);
    gemm64 <<<dim3(4, 64), 256>>>(ffn, f2_w, f2_b, t2, BQd, CCd, DFFd, 0);
    add_ln<<<BQd, 256>>>(tgt2, t2, ln3_g, ln3_b, out);
}

// round 5
// speedup vs baseline: 2.9915x; 1.4316x over previous
#include <cuda_runtime.h>
#include <math.h>
#include <stdint.h>

#define BB   4
#define LQd  1024
#define CCd  256
#define HHd  8
#define DHd  32
#define LLd  4
#define PPd  4
#define DFFd 1024
#define LSRCd 21760
#define BQd  (BB*LQd)   // 4096

// ------------------------- scratch (device globals; no allocs) ---------------
__device__ float g_qk    [BQd*CCd];
__device__ float g_qkproj[BQd*512];          // fused Q|K projection
__device__ float g_v     [BQd*CCd];
__device__ float g_o     [BQd*CCd];
__device__ float g_t2    [BQd*CCd];
__device__ float g_tgt1  [BQd*CCd];
__device__ float g_query [BQd*CCd];
__device__ float g_value [(size_t)BB*LSRCd*CCd];   // 89 MB
__device__ float g_offaw [BQd*384];          // fused offsets|attn-weights
__device__ float g_woffaw[384*CCd];
__device__ float g_boffaw[384];
__device__ float g_samp  [BQd*CCd];
__device__ float g_tgt2  [BQd*CCd];
__device__ float g_ffn   [BQd*DFFd];

// ------------------------- elementwise add -----------------------------------
__global__ void vec_add(const float* __restrict__ a, const float* __restrict__ b,
                        float* __restrict__ c, int n) {
    int i = blockIdx.x * blockDim.x + threadIdx.x;
    if (i < n) c[i] = a[i] + b[i];
}

// ------------------------- TF32 tensor-core GEMM -----------------------------
// C = A @ W^T + bias.  A:(M,K) row-major, W:(N,K) row-major.
// 128x128 tile, BK=16, 256 threads = 8 warps (2x4), warp tile 64x32.
// mma.sync.m16n8k8 tf32. Smem stride 20 words -> conflict-free frag loads.
__device__ __forceinline__ uint32_t f2tf32(float x) {
    uint32_t r;
    asm("cvt.rna.tf32.f32 %0, %1;" : "=r"(r) : "f"(x));
    return r;
}

__device__ __forceinline__ void mma8(float4& d, const uint32_t* a, const uint32_t* b) {
    asm volatile("mma.sync.aligned.m16n8k8.row.col.f32.tf32.tf32.f32 "
                 "{%0,%1,%2,%3}, {%4,%5,%6,%7}, {%8,%9}, {%0,%1,%2,%3};"
                 : "+f"(d.x), "+f"(d.y), "+f"(d.z), "+f"(d.w)
                 : "r"(a[0]), "r"(a[1]), "r"(a[2]), "r"(a[3]),
                   "r"(b[0]), "r"(b[1]));
}

#define TSTR 20

__global__ __launch_bounds__(256) void gemm_tf32(
    const float* __restrict__ A, const float* __restrict__ W,
    const float* __restrict__ bias, float* __restrict__ C,
    int M, int N, int K, int relu)
{
    __shared__ uint32_t As[2][128][TSTR];
    __shared__ uint32_t Bs[2][128][TSTR];
    const int tid  = threadIdx.x;
    const int warp = tid >> 5, lane = tid & 31;
    const int g = lane >> 2, t = lane & 3;
    const int wm = (warp >> 2) * 64, wn = (warp & 3) * 32;
    const int m0 = blockIdx.y * 128, n0 = blockIdx.x * 128;
    const int r_ld = tid >> 2, c_ld = (tid & 3) * 4;

    const float* Ap = A + (size_t)(m0 + r_ld) * K + c_ld;
    const float* Wp = W + (size_t)(n0 + r_ld) * K + c_ld;

    float4 acc[4][4];
#pragma unroll
    for (int i = 0; i < 4; i++)
#pragma unroll
        for (int j = 0; j < 4; j++) acc[i][j] = make_float4(0.f, 0.f, 0.f, 0.f);

    // initial tile -> buffer 0
    {
#pragma unroll
        for (int i = 0; i < 2; i++) {
            float4 a = *(const float4*)(Ap + (size_t)(64 * i) * K);
            float4 b = *(const float4*)(Wp + (size_t)(64 * i) * K);
            uint32_t* as = &As[0][r_ld + 64 * i][c_ld];
            uint32_t* bs = &Bs[0][r_ld + 64 * i][c_ld];
            as[0] = f2tf32(a.x); as[1] = f2tf32(a.y); as[2] = f2tf32(a.z); as[3] = f2tf32(a.w);
            bs[0] = f2tf32(b.x); bs[1] = f2tf32(b.y); bs[2] = f2tf32(b.z); bs[3] = f2tf32(b.w);
        }
    }
    __syncthreads();

    int buf = 0;
    for (int k0 = 16; k0 < K; k0 += 16) {
        // prefetch next tile to registers
        float4 pa0 = *(const float4*)(Ap + k0);
        float4 pa1 = *(const float4*)(Ap + (size_t)64 * K + k0);
        float4 pb0 = *(const float4*)(Wp + k0);
        float4 pb1 = *(const float4*)(Wp + (size_t)64 * K + k0);

        // compute on current buffer
#pragma unroll
        for (int ks = 0; ks < 2; ks++) {
            const int kk = ks * 8;
            uint32_t af[4][4], bf[4][2];
#pragma unroll
            for (int mf = 0; mf < 4; mf++) {
                af[mf][0] = As[buf][wm + mf * 16 + g    ][kk + t];
                af[mf][1] = As[buf][wm + mf * 16 + g + 8][kk + t];
                af[mf][2] = As[buf][wm + mf * 16 + g    ][kk + t + 4];
                af[mf][3] = As[buf][wm + mf * 16 + g + 8][kk + t + 4];
            }
#pragma unroll
            for (int nf = 0; nf < 4; nf++) {
                bf[nf][0] = Bs[buf][wn + nf * 8 + g][kk + t];
                bf[nf][1] = Bs[buf][wn + nf * 8 + g][kk + t + 4];
            }
#pragma unroll
            for (int mf = 0; mf < 4; mf++)
#pragma unroll
                for (int nf = 0; nf < 4; nf++)
                    mma8(acc[mf][nf], af[mf], bf[nf]);
        }

        // store prefetched tile to other buffer
        {
            uint32_t* as = &As[buf ^ 1][r_ld][c_ld];
            uint32_t* bs = &Bs[buf ^ 1][r_ld][c_ld];
            as[0] = f2tf32(pa0.x); as[1] = f2tf32(pa0.y); as[2] = f2tf32(pa0.z); as[3] = f2tf32(pa0.w);
            bs[0] = f2tf32(pb0.x); bs[1] = f2tf32(pb0.y); bs[2] = f2tf32(pb0.z); bs[3] = f2tf32(pb0.w);
            uint32_t* as2 = &As[buf ^ 1][r_ld + 64][c_ld];
            uint32_t* bs2 = &Bs[buf ^ 1][r_ld + 64][c_ld];
            as2[0] = f2tf32(pa1.x); as2[1] = f2tf32(pa1.y); as2[2] = f2tf32(pa1.z); as2[3] = f2tf32(pa1.w);
            bs2[0] = f2tf32(pb1.x); bs2[1] = f2tf32(pb1.y); bs2[2] = f2tf32(pb1.z); bs2[3] = f2tf32(pb1.w);
        }
        __syncthreads();
        buf ^= 1;
    }

    // last tile
#pragma unroll
    for (int ks = 0; ks < 2; ks++) {
        const int kk = ks * 8;
        uint32_t af[4][4], bf[4][2];
#pragma unroll
        for (int mf = 0; mf < 4; mf++) {
            af[mf][0] = As[buf][wm + mf * 16 + g    ][kk + t];
            af[mf][1] = As[buf][wm + mf * 16 + g + 8][kk + t];
            af[mf][2] = As[buf][wm + mf * 16 + g    ][kk + t + 4];
            af[mf][3] = As[buf][wm + mf * 16 + g + 8][kk + t + 4];
        }
#pragma unroll
        for (int nf = 0; nf < 4; nf++) {
            bf[nf][0] = Bs[buf][wn + nf * 8 + g][kk + t];
            bf[nf][1] = Bs[buf][wn + nf * 8 + g][kk + t + 4];
        }
#pragma unroll
        for (int mf = 0; mf < 4; mf++)
#pragma unroll
            for (int nf = 0; nf < 4; nf++)
                mma8(acc[mf][nf], af[mf], bf[nf]);
    }

    // epilogue
#pragma unroll
    for (int mf = 0; mf < 4; mf++) {
        int row = m0 + wm + mf * 16 + g;
#pragma unroll
        for (int nf = 0; nf < 4; nf++) {
            int col = n0 + wn + nf * 8 + 2 * t;
            float b0 = bias[col], b1 = bias[col + 1];
            float4 v = acc[mf][nf];
            float2 lo = make_float2(v.x + b0, v.y + b1);
            float2 hi = make_float2(v.z + b0, v.w + b1);
            if (relu) {
                lo.x = fmaxf(lo.x, 0.f); lo.y = fmaxf(lo.y, 0.f);
                hi.x = fmaxf(hi.x, 0.f); hi.y = fmaxf(hi.y, 0.f);
            }
            *(float2*)&C[(size_t)row * N + col]       = lo;
            *(float2*)&C[(size_t)(row + 8) * N + col] = hi;
        }
    }
}

// ------------------------- flash attention -----------------------------------
// grid (LQ/64=16, B*H=32), block 256. Q,K from fused proj (stride 512), V stride 256.
__global__ void flash_attn(const float* __restrict__ qkproj, const float* __restrict__ vsrc,
                           float* __restrict__ O)
{
    __shared__ __align__(16) float Qs[32][68];
    __shared__ __align__(16) float Ks[32][68];
    __shared__ __align__(16) float Vs[64][36];
    __shared__ __align__(16) float Ps[64][68];
    const int bh = blockIdx.y, b = bh >> 3, h = bh & 7;
    const int q0 = blockIdx.x * 64;
    const int tid = threadIdx.x;
    const int tx = tid & 15, ty = tid >> 4;
    const float SC = 0.1767766952966368932f;

    const float* qp = qkproj + (size_t)b * LQd * 512 + h * DHd;
    const float* kp = qkproj + (size_t)b * LQd * 512 + 256 + h * DHd;
    const float* vp = vsrc + (size_t)b * LQd * CCd + h * DHd;

#pragma unroll
    for (int i = 0; i < 8; i++) {
        int idx = tid + i * 256;
        int row = idx >> 5, d = idx & 31;
        Qs[d][row] = qp[(size_t)(q0 + row) * 512 + d];
    }
    float m_r[4], l_r[4], o_acc[4][2];
#pragma unroll
    for (int i = 0; i < 4; i++) { m_r[i] = -1e30f; l_r[i] = 0.f; o_acc[i][0] = 0.f; o_acc[i][1] = 0.f; }
    __syncthreads();

    for (int k0 = 0; k0 < LQd; k0 += 64) {
#pragma unroll
        for (int i = 0; i < 8; i++) {
            int idx = tid + i * 256;
            int row = idx >> 5, d = idx & 31;
            Ks[d][row] = kp[(size_t)(k0 + row) * 512 + d];
            Vs[row][d] = vp[(size_t)(k0 + row) * CCd + d];
        }
        __syncthreads();

        float s[4][4];
#pragma unroll
        for (int i = 0; i < 4; i++)
#pragma unroll
            for (int j = 0; j < 4; j++) s[i][j] = 0.f;
#pragma unroll
        for (int d = 0; d < 32; d++) {
            float a[4], w[4];
            *(float4*)(a) = *(const float4*)&Qs[d][ty * 4];
            *(float4*)(w) = *(const float4*)&Ks[d][tx * 4];
#pragma unroll
            for (int i = 0; i < 4; i++)
#pragma unroll
                for (int j = 0; j < 4; j++) s[i][j] += a[i] * w[j];
        }

#pragma unroll
        for (int i = 0; i < 4; i++) {
#pragma unroll
            for (int j = 0; j < 4; j++) s[i][j] *= SC;
            float mx = fmaxf(fmaxf(s[i][0], s[i][1]), fmaxf(s[i][2], s[i][3]));
            mx = fmaxf(mx, __shfl_xor_sync(0xffffffffu, mx, 1));
            mx = fmaxf(mx, __shfl_xor_sync(0xffffffffu, mx, 2));
            mx = fmaxf(mx, __shfl_xor_sync(0xffffffffu, mx, 4));
            mx = fmaxf(mx, __shfl_xor_sync(0xffffffffu, mx, 8));
            float mnew = fmaxf(m_r[i], mx);
            float cf = __expf(m_r[i] - mnew);
            float p0 = __expf(s[i][0] - mnew);
            float p1 = __expf(s[i][1] - mnew);
            float p2 = __expf(s[i][2] - mnew);
            float p3 = __expf(s[i][3] - mnew);
            float4 pv4 = make_float4(p0, p1, p2, p3);
            *(float4*)&Ps[ty * 4 + i][tx * 4] = pv4;
            float rs = p0 + p1 + p2 + p3;
            rs += __shfl_xor_sync(0xffffffffu, rs, 1);
            rs += __shfl_xor_sync(0xffffffffu, rs, 2);
            rs += __shfl_xor_sync(0xffffffffu, rs, 4);
            rs += __shfl_xor_sync(0xffffffffu, rs, 8);
            l_r[i] = l_r[i] * cf + rs;
            o_acc[i][0] *= cf; o_acc[i][1] *= cf;
            m_r[i] = mnew;
        }
        __syncthreads();

#pragma unroll
        for (int kk4 = 0; kk4 < 16; kk4++) {
            float p[4][4];
#pragma unroll
            for (int i = 0; i < 4; i++)
                *(float4*)(p[i]) = *(const float4*)&Ps[ty * 4 + i][kk4 * 4];
#pragma unroll
            for (int j = 0; j < 4; j++) {
                float2 vv = *(const float2*)&Vs[kk4 * 4 + j][tx * 2];
#pragma unroll
                for (int i = 0; i < 4; i++) {
                    o_acc[i][0] += p[i][j] * vv.x;
                    o_acc[i][1] += p[i][j] * vv.y;
                }
            }
        }
        __syncthreads();
    }

#pragma unroll
    for (int i = 0; i < 4; i++) {
        float inv = 1.f / l_r[i];
        float2 ov = make_float2(o_acc[i][0] * inv, o_acc[i][1] * inv);
        *(float2*)&O[(size_t)(b * LQd + q0 + ty * 4 + i) * CCd + h * DHd + tx * 2] = ov;
    }
}

// ------------------------- fused residual + LayerNorm ------------------------
__global__ void add_ln(const float* __restrict__ a, const float* __restrict__ b,
                       const float* __restrict__ g, const float* __restrict__ bet,
                       float* __restrict__ out)
{
    __shared__ float sh[256];
    int row = blockIdx.x, t = threadIdx.x;
    size_t idx = (size_t)row * CCd + t;
    float v = a[idx] + b[idx];
    sh[t] = v; __syncthreads();
    for (int s = 128; s > 0; s >>= 1) { if (t < s) sh[t] += sh[t + s]; __syncthreads(); }
    float mean = sh[0] * (1.f / 256.f);
    __syncthreads();
    float d = v - mean;
    sh[t] = d * d; __syncthreads();
    for (int s = 128; s > 0; s >>= 1) { if (t < s) sh[t] += sh[t + s]; __syncthreads(); }
    float var = sh[0] * (1.f / 256.f);
    out[idx] = d * rsqrtf(var + 1e-5f) * g[t] + bet[t];
}

// ------------------------- attention-weight softmax over L*P=16 --------------
__global__ void aw_softmax(float* __restrict__ a)
{
    int gi = blockIdx.x * blockDim.x + threadIdx.x;
    if (gi >= BQd * HHd) return;
    int bq = gi >> 3, h = gi & 7;
    float* p = a + (size_t)bq * 384 + 256 + h * 16;
    float x[16];
    float m = -1e30f;
#pragma unroll
    for (int i = 0; i < 16; i++) { x[i] = p[i]; m = fmaxf(m, x[i]); }
    float s = 0.f;
#pragma unroll
    for (int i = 0; i < 16; i++) { x[i] = __expf(x[i] - m); s += x[i]; }
    float inv = 1.f / s;
#pragma unroll
    for (int i = 0; i < 16; i++) p[i] = x[i] * inv;
}

// ------------------------- multi-scale deformable sampling -------------------
__global__ void deform_sample(const float* __restrict__ value, const float* __restrict__ ref,
                              const float* __restrict__ offaw, float* __restrict__ out)
{
    const int levH[4] = {128, 64, 32, 16};
    const int levW[4] = {128, 64, 32, 16};
    const int levS[4] = {0, 16384, 20480, 21504};
    int bq = blockIdx.x;
    int b  = bq >> 10;
    int h  = threadIdx.x >> 5;
    int d  = threadIdx.x & 31;
    float acc = 0.f;
#pragma unroll
    for (int l = 0; l < 4; l++) {
        float rx = ref[((size_t)bq * LLd + l) * 2 + 0];
        float ry = ref[((size_t)bq * LLd + l) * 2 + 1];
        int w = levW[l], hh = levH[l], st = levS[l];
        float fw = (float)w, fh = (float)hh;
#pragma unroll
        for (int p = 0; p < 4; p++) {
            size_t oidx = (size_t)bq * 384 + h * 32 + (l * 4 + p) * 2;
            float lx = rx + offaw[oidx]     / fw;
            float ly = ry + offaw[oidx + 1] / fh;
            float x = lx * fw - 0.5f;
            float y = ly * fh - 0.5f;
            float x0f = floorf(x), y0f = floorf(y);
            int x0 = (int)x0f, y0 = (int)y0f;
            float wx1 = x - x0f, wx0 = 1.f - wx1;
            float wy1 = y - y0f, wy0 = 1.f - wy1;
            float a = offaw[(size_t)bq * 384 + 256 + h * 16 + l * 4 + p];
            float s = 0.f;
#pragma unroll
            for (int cy = 0; cy < 2; cy++) {
#pragma unroll
                for (int cx = 0; cx < 2; cx++) {
                    int ix = x0 + cx, iy = y0 + cy;
                    if (ix >= 0 && ix < w && iy >= 0 && iy < hh) {
                        float wgt = (cx ? wx1 : wx0) * (cy ? wy1 : wy0);
                        size_t vidx = (((size_t)(b * LSRCd + st + iy * w + ix)) * HHd + h) * DHd + d;
                        s += wgt * value[vidx];
                    }
                }
            }
            acc += a * s;
        }
    }
    out[(size_t)bq * CCd + h * DHd + d] = acc;
}

// ------------------------- launch --------------------------------------------
extern "C" void kernel_launch(void* const* d_in, const int* in_sizes, int n_in,
                              void* d_out, int out_size)
{
    (void)in_sizes; (void)n_in; (void)out_size;
    const float* tgt   = (const float*)d_in[0];
    const float* qpos  = (const float*)d_in[1];
    const float* ref   = (const float*)d_in[2];
    const float* src   = (const float*)d_in[3];
    const float* in_w  = (const float*)d_in[4];
    const float* in_b  = (const float*)d_in[5];
    const float* sa_w  = (const float*)d_in[6];
    const float* sa_b  = (const float*)d_in[7];
    const float* off_w = (const float*)d_in[8];
    const float* off_b = (const float*)d_in[9];
    const float* aw_w  = (const float*)d_in[10];
    const float* aw_b  = (const float*)d_in[11];
    const float* val_w = (const float*)d_in[12];
    const float* val_b = (const float*)d_in[13];
    const float* co_w  = (const float*)d_in[14];
    const float* co_b  = (const float*)d_in[15];
    const float* ln1_g = (const float*)d_in[16];
    const float* ln1_b = (const float*)d_in[17];
    const float* ln2_g = (const float*)d_in[18];
    const float* ln2_b = (const float*)d_in[19];
    const float* ln3_g = (const float*)d_in[20];
    const float* ln3_b = (const float*)d_in[21];
    const float* f1_w  = (const float*)d_in[22];
    const float* f1_b  = (const float*)d_in[23];
    const float* f2_w  = (const float*)d_in[24];
    const float* f2_b  = (const float*)d_in[25];
    float* out = (float*)d_out;

    float *qk, *qkproj, *v, *o, *t2, *tgt1, *query, *value, *offaw, *woffaw, *boffaw, *samp, *tgt2, *ffn;
    cudaGetSymbolAddress((void**)&qk,     g_qk);
    cudaGetSymbolAddress((void**)&qkproj, g_qkproj);
    cudaGetSymbolAddress((void**)&v,      g_v);
    cudaGetSymbolAddress((void**)&o,      g_o);
    cudaGetSymbolAddress((void**)&t2,     g_t2);
    cudaGetSymbolAddress((void**)&tgt1,   g_tgt1);
    cudaGetSymbolAddress((void**)&query,  g_query);
    cudaGetSymbolAddress((void**)&value,  g_value);
    cudaGetSymbolAddress((void**)&offaw,  g_offaw);
    cudaGetSymbolAddress((void**)&woffaw, g_woffaw);
    cudaGetSymbolAddress((void**)&boffaw, g_boffaw);
    cudaGetSymbolAddress((void**)&samp,   g_samp);
    cudaGetSymbolAddress((void**)&tgt2,   g_tgt2);
    cudaGetSymbolAddress((void**)&ffn,    g_ffn);

    const int NTOT = BQd * CCd;

    // fuse off/aw weights into one (384,256) matrix + (384,) bias
    cudaMemcpyAsync(woffaw,             off_w, 256 * 256 * sizeof(float), cudaMemcpyDeviceToDevice);
    cudaMemcpyAsync(woffaw + 256 * 256, aw_w,  128 * 256 * sizeof(float), cudaMemcpyDeviceToDevice);
    cudaMemcpyAsync(boffaw,             off_b, 256 * sizeof(float),       cudaMemcpyDeviceToDevice);
    cudaMemcpyAsync(boffaw + 256,       aw_b,  128 * sizeof(float),       cudaMemcpyDeviceToDevice);

    // ---- self-attention ----
    vec_add<<<NTOT / 256, 256>>>(tgt, qpos, qk, NTOT);
    gemm_tf32<<<dim3(4, 32), 256>>>(qk, in_w, in_b, qkproj, BQd, 512, CCd, 0);      // fused Q|K
    gemm_tf32<<<dim3(2, 32), 256>>>(tgt, in_w + 2 * CCd * CCd, in_b + 2 * CCd, v, BQd, CCd, CCd, 0);
    flash_attn<<<dim3(16, 32), 256>>>(qkproj, v, o);
    gemm_tf32<<<dim3(2, 32), 256>>>(o, sa_w, sa_b, t2, BQd, CCd, CCd, 0);
    add_ln<<<BQd, 256>>>(tgt, t2, ln2_g, ln2_b, tgt1);

    // ---- deformable cross-attention ----
    vec_add<<<NTOT / 256, 256>>>(tgt1, qpos, query, NTOT);
    gemm_tf32<<<dim3(2, 680), 256>>>(src, val_w, val_b, value, BB * LSRCd, CCd, CCd, 0);
    gemm_tf32<<<dim3(3, 32), 256>>>(query, woffaw, boffaw, offaw, BQd, 384, CCd, 0); // fused off|aw
    aw_softmax<<<(BQd * HHd + 255) / 256, 256>>>(offaw);
    deform_sample<<<BQd, 256>>>(value, ref, offaw, samp);
    gemm_tf32<<<dim3(2, 32), 256>>>(samp, co_w, co_b, t2, BQd, CCd, CCd, 0);
    add_ln<<<BQd, 256>>>(tgt1, t2, ln1_g, ln1_b, tgt2);

    // ---- FFN ----
    gemm_tf32<<<dim3(8, 32), 256>>>(tgt2, f1_w, f1_b, ffn, BQd, DFFd, CCd, 1);
    gemm_tf32<<<dim3(2, 32), 256>>>(ffn, f2_w, f2_b, t2, BQd, CCd, DFFd, 0);
    add_ln<<<BQd, 256>>>(tgt2, t2, ln3_g, ln3_b, out);
}